// round 4
// baseline (speedup 1.0000x reference)
#include <cuda_runtime.h>
#include <math.h>

#define B_ 32
#define S_ 2048
#define H_ 1024
#define NROWS (2 * B_ * S_)          // 131072 reward scalars
#define WARPS_PER_BLOCK 8
#define NBLOCKS (NROWS / WARPS_PER_BLOCK)   // 16384
#define BLOCKS_PER_BATCH (S_ / WARPS_PER_BLOCK)  // 256

// Scratch (allowed: __device__ globals, no allocation). 64-bit monotonic
// counters survive graph replays (gates use modulo tests, no resets needed).
__device__ float              g_rewards[NROWS];
__device__ float              g_per_pair[B_];
__device__ int                g_accflag[B_];
__device__ unsigned long long g_batch_cnt[2 * B_];
__device__ unsigned long long g_pair_cnt[B_];
__device__ unsigned long long g_fin_cnt;

__device__ __forceinline__ float warp_sum(float v) {
#pragma unroll
    for (int o = 16; o; o >>= 1) v += __shfl_xor_sync(0xffffffffu, v, o);
    return v;
}
__device__ __forceinline__ int warp_sum_i(int v) {
#pragma unroll
    for (int o = 16; o; o >>= 1) v += __shfl_xor_sync(0xffffffffu, v, o);
    return v;
}
__device__ __forceinline__ int warp_min_i(int v) {
#pragma unroll
    for (int o = 16; o; o >>= 1) v = min(v, __shfl_xor_sync(0xffffffffu, v, o));
    return v;
}

// ---------------------------------------------------------------------------
// Single fused kernel.
//  Phase A (all 16384 blocks): 8 rewards each (one warp per (batch,seq) dot).
//  Gate 1: block completing the 256th chunk of a batch bumps the pair counter;
//          the block completing the SECOND batch of a pair runs Phase B inline.
//  Phase B (32 scattered blocks): id scan + masked sigmoid sums for one pair.
//  Gate 2: 32nd pair completion runs the deterministic final reduction.
// ---------------------------------------------------------------------------
__global__ void __launch_bounds__(WARPS_PER_BLOCK * 32)
fused_kernel(const int* __restrict__ ids, const float* __restrict__ hs,
             const float* __restrict__ w, float* __restrict__ out) {
    const int tid  = threadIdx.x;
    const int warp = tid >> 5;
    const int lane = tid & 31;

    __shared__ float4 sw[H_ / 4];
    __shared__ int    s_pair;      // pair this block must execute, or -1
    __shared__ int    sc, sr, sd;
    __shared__ float  sl[8], ss1[8], ss2[8];
    __shared__ int    sn[8];
    __shared__ bool   s_final;

    // ---- Phase A: 8 reward dots (one per warp) ----
    for (int i = tid; i < H_ / 4; i += blockDim.x)
        sw[i] = reinterpret_cast<const float4*>(w)[i];
    __syncthreads();

    const int row = blockIdx.x * WARPS_PER_BLOCK + warp;   // grid is exact
    {
        const float4* __restrict__ hp =
            reinterpret_cast<const float4*>(hs + (size_t)row * H_);
        float acc = 0.0f;
#pragma unroll
        for (int i = 0; i < 8; i++) {
            float4 h  = __ldcs(&hp[lane + i * 32]);   // streaming, no reuse
            float4 ww = sw[lane + i * 32];
            acc += h.x * ww.x + h.y * ww.y + h.z * ww.z + h.w * ww.w;
        }
        acc = warp_sum(acc);
        if (lane == 0) g_rewards[row] = acc;
    }

    // ---- Gate 1: publish this block's rewards, detect batch completion ----
    __threadfence();
    __syncthreads();
    const int batch = blockIdx.x / BLOCKS_PER_BATCH;        // 0..63
    if (tid == 0) {
        int pair_todo = -1;
        unsigned long long pb = atomicAdd(&g_batch_cnt[batch], 1ULL);
        if (pb % BLOCKS_PER_BATCH == BLOCKS_PER_BATCH - 1) {
            // this block completed batch `batch`
            int p = (batch < B_) ? batch : batch - B_;
            unsigned long long pp = atomicAdd(&g_pair_cnt[p], 1ULL);
            if (pp % 2 == 1) pair_todo = p;   // both batches of pair p done
        }
        s_pair = pair_todo;
    }
    __syncthreads();

    const int p = s_pair;
    if (p < 0) return;

    // ---- Phase B: execute pair p (rewards now L2-hot and visible) ----
    __threadfence();   // acquire
    if (tid == 0) { sc = S_; sr = S_; sd = S_; }
    __syncthreads();

    {   // id scan: 2 rows x 512 int4, 4 vectors per thread
        const int4* __restrict__ idc =
            reinterpret_cast<const int4*>(ids + (size_t)p * S_);
        const int4* __restrict__ idr =
            reinterpret_cast<const int4*>(ids + (size_t)(B_ + p) * S_);
        int cmin = S_, rmin = S_, dmin = S_;
#pragma unroll
        for (int it = 0; it < 2; it++) {
            int v = tid + it * 256;
            int4 c4 = idc[v], r4 = idr[v];
            int s = v * 4;
            if (c4.w == 0) cmin = min(cmin, s + 3);
            if (c4.z == 0) cmin = min(cmin, s + 2);
            if (c4.y == 0) cmin = min(cmin, s + 1);
            if (c4.x == 0) cmin = min(cmin, s + 0);
            if (r4.w == 0) rmin = min(rmin, s + 3);
            if (r4.z == 0) rmin = min(rmin, s + 2);
            if (r4.y == 0) rmin = min(rmin, s + 1);
            if (r4.x == 0) rmin = min(rmin, s + 0);
            if (c4.w != r4.w) dmin = min(dmin, s + 3);
            if (c4.z != r4.z) dmin = min(dmin, s + 2);
            if (c4.y != r4.y) dmin = min(dmin, s + 1);
            if (c4.x != r4.x) dmin = min(dmin, s + 0);
        }
        cmin = warp_min_i(cmin);
        rmin = warp_min_i(rmin);
        dmin = warp_min_i(dmin);
        if (lane == 0) {
            if (cmin < S_) atomicMin(&sc, cmin);
            if (rmin < S_) atomicMin(&sr, rmin);
            if (dmin < S_) atomicMin(&sd, dmin);
        }
    }
    __syncthreads();

    const int  c_ind     = sc;
    const int  r_ind_pad = sr;
    const bool has_div   = sd < S_;
    const int  div_ind   = has_div ? sd : (S_ - 1);
    const int  r_ind     = has_div ? r_ind_pad : c_ind;
    const int  end_ind   = has_div ? max(c_ind, r_ind_pad) : S_;

    const float* __restrict__ rwc = g_rewards + (size_t)p * S_;
    const float* __restrict__ rwr = g_rewards + (size_t)(B_ + p) * S_;

    float lsum = 0.0f, csum = 0.0f, rsum = 0.0f;
    int   cnt_local = 0;
    for (int s = div_ind + tid; s < end_ind; s += 256) {
        float rc = rwc[s], rr = rwr[s];
        float x  = rc - rr;
        // log_sigmoid(x) = min(x,0) - log1p(exp(-|x|))
        lsum += fminf(x, 0.0f) - log1pf(__expf(-fabsf(x)));
        csum += __fdividef(1.0f, 1.0f + __expf(-rc));
        rsum += __fdividef(1.0f, 1.0f + __expf(-rr));
        cnt_local++;
    }
    float wl = warp_sum(lsum), wc = warp_sum(csum), wr = warp_sum(rsum);
    int   wn = warp_sum_i(cnt_local);
    if (lane == 0) { sl[warp] = wl; ss1[warp] = wc; ss2[warp] = wr; sn[warp] = wn; }
    __syncthreads();

    if (tid == 0) {
        float L = 0, C = 0, R = 0; int N = 0;
#pragma unroll
        for (int i = 0; i < 8; i++) { L += sl[i]; C += ss1[i]; R += ss2[i]; N += sn[i]; }
        float cnt = fmaxf((float)N, 1.0f);
        g_per_pair[p] = L / cnt;
        g_accflag[p]  = ((C - R) / cnt > 0.5f) ? 1 : 0;
        int ci = c_ind - 1; if (ci < 0) ci = 0; if (ci >= S_) ci = S_ - 1;
        int ri = r_ind - 1; if (ri < 0) ri = 0; if (ri >= S_) ri = S_ - 1;
        out[2 + p]      = rwc[ci];   // chosen_mean_score
        out[2 + B_ + p] = rwr[ri];   // rejected_mean_score
        // ---- Gate 2: last pair triggers final reduction ----
        __threadfence();
        unsigned long long pf = atomicAdd(&g_fin_cnt, 1ULL);
        s_final = (pf % B_ == B_ - 1);
    }
    __syncthreads();

    if (s_final && tid < 32) {
        __threadfence();   // acquire other pairs' scratch
        float pp = g_per_pair[tid];
        int   af = g_accflag[tid];
        float ls = warp_sum(pp);
        int   ac = warp_sum_i(af);
        if (tid == 0) {
            out[0] = -ls;          // loss
            out[1] = (float)ac;    // acc
        }
    }
}

// ---------------------------------------------------------------------------
extern "C" void kernel_launch(void* const* d_in, const int* in_sizes, int n_in,
                              void* d_out, int out_size) {
    const int*   ids = (const int*)d_in[0];     // input_ids  (2B, S) int32
    const float* hs  = (const float*)d_in[1];   // hidden     (2B, S, H) f32
    const float* w   = (const float*)d_in[2];   // w          (H,) f32
    float* out = (float*)d_out;

    fused_kernel<<<NBLOCKS, WARPS_PER_BLOCK * 32>>>(ids, hs, w, out);
}

// round 5
// speedup vs baseline: 1.0470x; 1.0470x over previous
#include <cuda_runtime.h>
#include <math.h>

#define B_ 32
#define S_ 2048
#define H_ 1024
#define NROWS (2 * B_ * S_)   // 131072
#define WARPS_PER_BLOCK 8

// Scratch (allowed: __device__ globals, no allocation)
__device__ float    g_rewards[NROWS];
__device__ float    g_per_pair[B_];
__device__ int      g_accflag[B_];
__device__ int      g_sc[B_], g_sr[B_], g_sd[B_];
__device__ unsigned g_done;

__device__ __forceinline__ float warp_sum(float v) {
#pragma unroll
    for (int o = 16; o; o >>= 1) v += __shfl_xor_sync(0xffffffffu, v, o);
    return v;
}
__device__ __forceinline__ int warp_sum_i(int v) {
#pragma unroll
    for (int o = 16; o; o >>= 1) v += __shfl_xor_sync(0xffffffffu, v, o);
    return v;
}
__device__ __forceinline__ int warp_min_i(int v) {
#pragma unroll
    for (int o = 16; o; o >>= 1) v = min(v, __shfl_xor_sync(0xffffffffu, v, o));
    return v;
}

// ---------------------------------------------------------------------------
// Kernel 1: rewards[row] = dot(hidden[row, :], w)   (HBM-bound, 512 MB read)
// One warp per row, flat grid. Blocks 0..31 ALSO scan the id pair `blockIdx.x`
// (16 KB) and publish c_ind/r_ind_pad/div_min — fully hidden under the HBM
// stream (issue was only 20.7% busy). Plain single-writer stores; the kernel
// boundary makes them visible to pair_kernel. Block 0 resets g_done.
// ---------------------------------------------------------------------------
__global__ void __launch_bounds__(WARPS_PER_BLOCK * 32)
reward_dot_kernel(const int* __restrict__ ids, const float* __restrict__ hs,
                  const float* __restrict__ w) {
    const int tid  = threadIdx.x;
    const int warp = tid >> 5;
    const int lane = tid & 31;

    if (blockIdx.x == 0 && tid == 0) g_done = 0;

    __shared__ float4 sw[H_ / 4];
    for (int i = tid; i < H_ / 4; i += blockDim.x)
        sw[i] = reinterpret_cast<const float4*>(w)[i];
    __syncthreads();

    // ---- main job: one reward dot per warp ----
    const int row = blockIdx.x * WARPS_PER_BLOCK + warp;   // grid exact
    {
        const float4* __restrict__ hp =
            reinterpret_cast<const float4*>(hs + (size_t)row * H_);
        float acc = 0.0f;
#pragma unroll
        for (int i = 0; i < 8; i++) {
            float4 h  = __ldcs(&hp[lane + i * 32]);   // streaming, no reuse
            float4 ww = sw[lane + i * 32];
            acc += h.x * ww.x + h.y * ww.y + h.z * ww.z + h.w * ww.w;
        }
        acc = warp_sum(acc);
        if (lane == 0) g_rewards[row] = acc;
    }

    // ---- side job (blocks 0..31): id scan for pair p = blockIdx.x ----
    if (blockIdx.x < B_) {
        const int p = blockIdx.x;
        __shared__ int sc, sr, sd;
        if (tid == 0) { sc = S_; sr = S_; sd = S_; }
        __syncthreads();

        const int4* __restrict__ idc =
            reinterpret_cast<const int4*>(ids + (size_t)p * S_);
        const int4* __restrict__ idr =
            reinterpret_cast<const int4*>(ids + (size_t)(B_ + p) * S_);
        int cmin = S_, rmin = S_, dmin = S_;
#pragma unroll
        for (int it = 0; it < 2; it++) {           // 512 int4 per row / 256 thr
            int v = tid + it * 256;
            int4 c4 = idc[v], r4 = idr[v];
            int s = v * 4;
            if (c4.w == 0) cmin = min(cmin, s + 3);
            if (c4.z == 0) cmin = min(cmin, s + 2);
            if (c4.y == 0) cmin = min(cmin, s + 1);
            if (c4.x == 0) cmin = min(cmin, s + 0);
            if (r4.w == 0) rmin = min(rmin, s + 3);
            if (r4.z == 0) rmin = min(rmin, s + 2);
            if (r4.y == 0) rmin = min(rmin, s + 1);
            if (r4.x == 0) rmin = min(rmin, s + 0);
            if (c4.w != r4.w) dmin = min(dmin, s + 3);
            if (c4.z != r4.z) dmin = min(dmin, s + 2);
            if (c4.y != r4.y) dmin = min(dmin, s + 1);
            if (c4.x != r4.x) dmin = min(dmin, s + 0);
        }
        cmin = warp_min_i(cmin);
        rmin = warp_min_i(rmin);
        dmin = warp_min_i(dmin);
        if (lane == 0) {
            if (cmin < S_) atomicMin(&sc, cmin);
            if (rmin < S_) atomicMin(&sr, rmin);
            if (dmin < S_) atomicMin(&sd, dmin);
        }
        __syncthreads();
        if (tid == 0) { g_sc[p] = sc; g_sr[p] = sr; g_sd[p] = sd; }
    }
}

// ---------------------------------------------------------------------------
// Kernel 2: per-pair masked sums only (indices precomputed) + fused finalize.
// One block of 1024 threads per pair; rewards are L2-hot.
// ---------------------------------------------------------------------------
__global__ void __launch_bounds__(1024)
pair_kernel(float* __restrict__ out) {
    const int b    = blockIdx.x;
    const int tid  = threadIdx.x;
    const int warp = tid >> 5;
    const int lane = tid & 31;

    __shared__ float s_rc[S_];
    __shared__ float s_rr[S_];
    __shared__ int   s_idx[3];
    __shared__ float sl[32], ss1[32], ss2[32];
    __shared__ int   sn[32];

    // indices (single L2 hit, broadcast via smem)
    if (tid == 0) { s_idx[0] = g_sc[b]; s_idx[1] = g_sr[b]; s_idx[2] = g_sd[b]; }

    // stage both reward rows: 1024 threads x 1 float4
    {
        const float4* __restrict__ rc4 =
            reinterpret_cast<const float4*>(g_rewards + (size_t)b * S_);
        const float4* __restrict__ rr4 =
            reinterpret_cast<const float4*>(g_rewards + (size_t)(B_ + b) * S_);
        if (tid < 512) reinterpret_cast<float4*>(s_rc)[tid]       = rc4[tid];
        else           reinterpret_cast<float4*>(s_rr)[tid - 512] = rr4[tid - 512];
    }
    __syncthreads();

    const int  c_ind     = s_idx[0];
    const int  r_ind_pad = s_idx[1];
    const bool has_div   = s_idx[2] < S_;
    const int  div_ind   = has_div ? s_idx[2] : (S_ - 1);
    const int  r_ind     = has_div ? r_ind_pad : c_ind;
    const int  end_ind   = has_div ? max(c_ind, r_ind_pad) : S_;

    float lsum = 0.0f, csum = 0.0f, rsum = 0.0f;
    int   cnt_local = 0;
    for (int s = div_ind + tid; s < end_ind; s += 1024) {
        float rc = s_rc[s], rr = s_rr[s];
        float x  = rc - rr;
        // log_sigmoid(x) = min(x,0) - log1p(exp(-|x|))
        lsum += fminf(x, 0.0f) - log1pf(__expf(-fabsf(x)));
        csum += __fdividef(1.0f, 1.0f + __expf(-rc));
        rsum += __fdividef(1.0f, 1.0f + __expf(-rr));
        cnt_local++;
    }

    float wl = warp_sum(lsum), wc = warp_sum(csum), wr = warp_sum(rsum);
    int   wn = warp_sum_i(cnt_local);
    if (lane == 0) { sl[warp] = wl; ss1[warp] = wc; ss2[warp] = wr; sn[warp] = wn; }
    __syncthreads();

    __shared__ bool s_last;
    if (tid == 0) {
        float L = 0, C = 0, R = 0; int N = 0;
#pragma unroll
        for (int i = 0; i < 32; i++) { L += sl[i]; C += ss1[i]; R += ss2[i]; N += sn[i]; }
        float cnt = fmaxf((float)N, 1.0f);
        g_per_pair[b] = L / cnt;
        g_accflag[b]  = ((C - R) / cnt > 0.5f) ? 1 : 0;
        int ci = c_ind - 1; if (ci < 0) ci = 0; if (ci >= S_) ci = S_ - 1;
        int ri = r_ind - 1; if (ri < 0) ri = 0; if (ri >= S_) ri = S_ - 1;
        out[2 + b]      = s_rc[ci];   // chosen_mean_score
        out[2 + B_ + b] = s_rr[ri];   // rejected_mean_score
        __threadfence();
        unsigned prev = atomicAdd(&g_done, 1u);
        s_last = (prev == (unsigned)(B_ - 1));
    }
    __syncthreads();

    // Last block to finish: deterministic final reduction (fixed order)
    if (s_last && tid < 32) {
        __threadfence();   // acquire other pairs' scratch
        float pp = g_per_pair[tid];
        int   af = g_accflag[tid];
        float ls = warp_sum(pp);
        int   ac = warp_sum_i(af);
        if (tid == 0) {
            out[0] = -ls;          // loss
            out[1] = (float)ac;    // acc
        }
    }
}

// ---------------------------------------------------------------------------
extern "C" void kernel_launch(void* const* d_in, const int* in_sizes, int n_in,
                              void* d_out, int out_size) {
    const int*   ids = (const int*)d_in[0];     // input_ids  (2B, S) int32
    const float* hs  = (const float*)d_in[1];   // hidden     (2B, S, H) f32
    const float* w   = (const float*)d_in[2];   // w          (H,) f32
    float* out = (float*)d_out;

    const int blocks = NROWS / WARPS_PER_BLOCK;   // 16384
    reward_dot_kernel<<<blocks, WARPS_PER_BLOCK * 32>>>(ids, hs, w);
    pair_kernel<<<B_, 1024>>>(out);
}